// round 7
// baseline (speedup 1.0000x reference)
#include <cuda_runtime.h>
#include <math.h>

#define NNODE 20000
#define NEDGE 400000
#define D_IN  1546
#define D_H   128
#define D_FF  512

// ---------------- scratch (device globals; no allocations) ----------------
__device__ float g_X [NNODE * D_IN];   // updated node features (1546)
__device__ float g_q [NNODE * D_H];
__device__ float g_k [NNODE * D_H];
__device__ float g_v [NNODE * D_H];
__device__ float g_h [NNODE * D_H];    // r accum -> h
__device__ float g_hi[NNODE * D_H];
__device__ float g_hj[NNODE * D_H];
__device__ float g_ln[NNODE * D_H];
__device__ float g_h2[NNODE * D_H];
__device__ float g_ff[NNODE * D_FF];
__device__ float g_att[NEDGE];
__device__ float g_part[512];
__device__ float g_red[2];             // [0]=max, [1]=sum

// ---------------- generic fp32 tiled GEMM: C = act(A*B + bias + resid) -----
// A: MxK row-major, B: KxN row-major, C: MxN. BM=BN=128, BK=16, 256 thr, 8x8.
template <int ACT>  // 0=none, 1=relu, 2=leaky(0.01)
__device__ __forceinline__ void gemm_body(
    const float* __restrict__ A, const float* __restrict__ B,
    const float* __restrict__ bias, const float* __restrict__ resid,
    float* __restrict__ C, int M, int N, int K)
{
    __shared__ float As[16][132];
    __shared__ float Bs[16][132];
    const int tid = threadIdx.x;
    const int rowBase = blockIdx.x * 128;
    const int colBase = blockIdx.y * 128;
    const int tx = tid & 15;   // 16 col groups
    const int ty = tid >> 4;   // 16 row groups

    float acc[8][8];
#pragma unroll
    for (int i = 0; i < 8; i++)
#pragma unroll
        for (int j = 0; j < 8; j++) acc[i][j] = 0.f;

    for (int k0 = 0; k0 < K; k0 += 16) {
#pragma unroll
        for (int jj = 0; jj < 8; jj++) {
            int l = tid + jj * 256;
            int r = l >> 4, c = l & 15;
            int gr = rowBase + r, gc = k0 + c;
            As[c][r] = (gr < M && gc < K) ? A[(size_t)gr * K + gc] : 0.f;
        }
#pragma unroll
        for (int jj = 0; jj < 8; jj++) {
            int l = tid + jj * 256;
            int r = l >> 7, c = l & 127;
            int gr = k0 + r, gc = colBase + c;
            Bs[r][c] = (gr < K && gc < N) ? B[(size_t)gr * N + gc] : 0.f;
        }
        __syncthreads();
#pragma unroll
        for (int kk = 0; kk < 16; kk++) {
            float a[8], b[8];
#pragma unroll
            for (int i = 0; i < 8; i++) a[i] = As[kk][ty * 8 + i];
#pragma unroll
            for (int j = 0; j < 8; j++) b[j] = Bs[kk][tx * 8 + j];
#pragma unroll
            for (int i = 0; i < 8; i++)
#pragma unroll
                for (int j = 0; j < 8; j++)
                    acc[i][j] = fmaf(a[i], b[j], acc[i][j]);
        }
        __syncthreads();
    }

#pragma unroll
    for (int i = 0; i < 8; i++) {
        int gr = rowBase + ty * 8 + i;
        if (gr >= M) continue;
#pragma unroll
        for (int j = 0; j < 8; j++) {
            int gc = colBase + tx * 8 + j;
            if (gc >= N) continue;
            float val = acc[i][j];
            if (bias)  val += bias[gc];
            if (resid) val += resid[(size_t)gr * N + gc];
            if (ACT == 1) val = fmaxf(val, 0.f);
            if (ACT == 2) val = (val > 0.f) ? val : 0.01f * val;
            C[(size_t)gr * N + gc] = val;
        }
    }
}

template <int ACT>
__global__ __launch_bounds__(256) void gemm_kernel(
    const float* __restrict__ A, const float* __restrict__ B,
    const float* bias, const float* resid, float* C, int M, int N, int K)
{
    gemm_body<ACT>(A, B, bias, resid, C, M, N, K);
}

// 6 projections fused over grid.z (shares A row-tiles through L2). N = D_H.
struct X6Args {
    const float* B[6];
    const float* bias[6];
    float*       C[6];
};
__global__ __launch_bounds__(256) void gemm_x6_kernel(
    const float* __restrict__ A, X6Args p, int M, int K)
{
    int z = blockIdx.z;
    gemm_body<0>(A, p.B[z], p.bias[z], nullptr, p.C[z], M, D_H, K);
}

// ---------------- LayerNorm over 128, warp per row -------------------------
__global__ __launch_bounds__(256) void ln128_kernel(
    const float* __restrict__ in, const float* __restrict__ gamma,
    const float* __restrict__ beta, float* __restrict__ out, int M)
{
    int row = blockIdx.x * 8 + (threadIdx.x >> 5);
    if (row >= M) return;
    int lane = threadIdx.x & 31;
    const float* p = in + (size_t)row * D_H;
    float v0 = p[lane], v1 = p[lane + 32], v2 = p[lane + 64], v3 = p[lane + 96];
    float s = v0 + v1 + v2 + v3;
#pragma unroll
    for (int o = 16; o > 0; o >>= 1) s += __shfl_xor_sync(0xFFFFFFFFu, s, o);
    float mean = s * (1.f / 128.f);
    float d0 = v0 - mean, d1 = v1 - mean, d2 = v2 - mean, d3 = v3 - mean;
    float ss = d0 * d0 + d1 * d1 + d2 * d2 + d3 * d3;
#pragma unroll
    for (int o = 16; o > 0; o >>= 1) ss += __shfl_xor_sync(0xFFFFFFFFu, ss, o);
    float inv = rsqrtf(ss * (1.f / 128.f) + 1e-5f);
    float* q = out + (size_t)row * D_H;
    q[lane]      = d0 * inv * gamma[lane]      + beta[lane];
    q[lane + 32] = d1 * inv * gamma[lane + 32] + beta[lane + 32];
    q[lane + 64] = d2 * inv * gamma[lane + 64] + beta[lane + 64];
    q[lane + 96] = d3 * inv * gamma[lane + 96] + beta[lane + 96];
}

// ---------------- edge kernels (warp per edge) ------------------------------
// NOTE: edge_index is int32 (JAX x64 disabled downcasts int64 -> int32).
__global__ __launch_bounds__(256) void att_dot_kernel(
    const int* __restrict__ ei, const float* __restrict__ q,
    const float* __restrict__ k, float* __restrict__ att, int E)
{
    int e = (blockIdx.x * blockDim.x + threadIdx.x) >> 5;
    if (e >= E) return;
    int lane = threadIdx.x & 31;
    size_t s = (size_t)ei[e];
    size_t d = (size_t)ei[E + e];
    const float* qp = q + d * D_H;
    const float* kp = k + s * D_H;
    float sum = qp[lane] * kp[lane] + qp[lane + 32] * kp[lane + 32] +
                qp[lane + 64] * kp[lane + 64] + qp[lane + 96] * kp[lane + 96];
#pragma unroll
    for (int o = 16; o > 0; o >>= 1) sum += __shfl_xor_sync(0xFFFFFFFFu, sum, o);
    if (lane == 0) att[e] = sum;
}

__global__ __launch_bounds__(256) void reduce_max_p1(
    const float* __restrict__ att, int E, float* __restrict__ part)
{
    __shared__ float sm[256];
    float m = -INFINITY;
    for (int i = blockIdx.x * 256 + threadIdx.x; i < E; i += gridDim.x * 256)
        m = fmaxf(m, att[i]);
    sm[threadIdx.x] = m;
    __syncthreads();
    for (int o = 128; o > 0; o >>= 1) {
        if (threadIdx.x < o) sm[threadIdx.x] = fmaxf(sm[threadIdx.x], sm[threadIdx.x + o]);
        __syncthreads();
    }
    if (threadIdx.x == 0) part[blockIdx.x] = sm[0];
}

__global__ __launch_bounds__(512) void reduce_max_p2(
    const float* __restrict__ part, float* __restrict__ out)
{
    __shared__ float sm[512];
    sm[threadIdx.x] = part[threadIdx.x];
    __syncthreads();
    for (int o = 256; o > 0; o >>= 1) {
        if (threadIdx.x < o) sm[threadIdx.x] = fmaxf(sm[threadIdx.x], sm[threadIdx.x + o]);
        __syncthreads();
    }
    if (threadIdx.x == 0) out[0] = sm[0];
}

__global__ __launch_bounds__(256) void reduce_sum_p1(
    const float* __restrict__ att, const float* __restrict__ maxp,
    int E, float* __restrict__ part)
{
    __shared__ float sm[256];
    float mx = maxp[0];
    float s = 0.f;
    for (int i = blockIdx.x * 256 + threadIdx.x; i < E; i += gridDim.x * 256)
        s += __expf(att[i] - mx);
    sm[threadIdx.x] = s;
    __syncthreads();
    for (int o = 128; o > 0; o >>= 1) {
        if (threadIdx.x < o) sm[threadIdx.x] += sm[threadIdx.x + o];
        __syncthreads();
    }
    if (threadIdx.x == 0) part[blockIdx.x] = sm[0];
}

__global__ __launch_bounds__(512) void reduce_sum_p2(
    const float* __restrict__ part, float* __restrict__ out)
{
    __shared__ float sm[512];
    sm[threadIdx.x] = part[threadIdx.x];
    __syncthreads();
    for (int o = 256; o > 0; o >>= 1) {
        if (threadIdx.x < o) sm[threadIdx.x] += sm[threadIdx.x + o];
        __syncthreads();
    }
    if (threadIdx.x == 0) out[0] = sm[0];
}

// msg = softmax(att) * v[src] * sigmoid(ea + hi[src] + hj[dst]); scatter-add h[dst]
__global__ __launch_bounds__(256) void message_kernel(
    const int* __restrict__ ei, const float* __restrict__ ea,
    const float* __restrict__ v, const float* __restrict__ hi,
    const float* __restrict__ hj, const float* __restrict__ att,
    const float* __restrict__ red, float* __restrict__ h, int E)
{
    int e = (blockIdx.x * blockDim.x + threadIdx.x) >> 5;
    if (e >= E) return;
    int lane = threadIdx.x & 31;
    size_t s = (size_t)ei[e];
    size_t d = (size_t)ei[E + e];
    float attn = __expf(att[e] - red[0]) * (1.f / red[1]);
    const float* eap = ea + (size_t)e * D_H;
    const float* vp  = v  + s * D_H;
    const float* hip = hi + s * D_H;
    const float* hjp = hj + d * D_H;
    float* hp = h + d * D_H;
#pragma unroll
    for (int c = 0; c < 4; c++) {
        int dim = lane + c * 32;
        float z = eap[dim] + hip[dim] + hjp[dim];
        float gate = 1.f / (1.f + __expf(-z));
        atomicAdd(&hp[dim], attn * vp[dim] * gate);
    }
}

// ---------------- launch ----------------------------------------------------
extern "C" void kernel_launch(void* const* d_in, const int* in_sizes, int n_in,
                              void* d_out, int out_size)
{
    const float* x    = (const float*)d_in[0];
    const int*   ei   = (const int*)d_in[1];   // int32 edge_index [2, E]
    const float* ea   = (const float*)d_in[2];
    const float* Wq   = (const float*)d_in[3];
    const float* bq   = (const float*)d_in[4];
    const float* Wk   = (const float*)d_in[5];
    const float* bk   = (const float*)d_in[6];
    const float* Wv   = (const float*)d_in[7];
    const float* bv   = (const float*)d_in[8];
    const float* Wr   = (const float*)d_in[9];
    const float* br   = (const float*)d_in[10];
    const float* Whi  = (const float*)d_in[11];
    const float* Whj  = (const float*)d_in[12];
    const float* g1   = (const float*)d_in[13];
    const float* be1  = (const float*)d_in[14];
    const float* W1   = (const float*)d_in[15];
    const float* bl1  = (const float*)d_in[16];
    const float* W2   = (const float*)d_in[17];
    const float* bl2  = (const float*)d_in[18];
    const float* g2   = (const float*)d_in[19];
    const float* be2  = (const float*)d_in[20];
    const float* Wlin = (const float*)d_in[21];
    const float* blin = (const float*)d_in[22];
    const float* Wlin2= (const float*)d_in[23];
    const float* blin2= (const float*)d_in[24];
    float* out = (float*)d_out;

    float *X, *q, *k, *v, *h, *hi, *hj, *ln, *h2, *ff, *att, *part, *red;
    cudaGetSymbolAddress((void**)&X,   g_X);
    cudaGetSymbolAddress((void**)&q,   g_q);
    cudaGetSymbolAddress((void**)&k,   g_k);
    cudaGetSymbolAddress((void**)&v,   g_v);
    cudaGetSymbolAddress((void**)&h,   g_h);
    cudaGetSymbolAddress((void**)&hi,  g_hi);
    cudaGetSymbolAddress((void**)&hj,  g_hj);
    cudaGetSymbolAddress((void**)&ln,  g_ln);
    cudaGetSymbolAddress((void**)&h2,  g_h2);
    cudaGetSymbolAddress((void**)&ff,  g_ff);
    cudaGetSymbolAddress((void**)&att, g_att);
    cudaGetSymbolAddress((void**)&part,g_part);
    cudaGetSymbolAddress((void**)&red, g_red);

    const int M = NNODE, E = NEDGE;
    const int rowTiles = (M + 127) / 128;           // 157
    const int edgeBlocks = (E * 32 + 255) / 256;    // warp per edge
    const int lnBlocks = (M + 7) / 8;

    const float* xin = x;
    for (int i = 0; i < 2; i++) {
        // 1) fused 6-way projection: q,k,v,r(->h),hi,hj
        X6Args a;
        a.B[0] = Wq  + (size_t)i * D_IN * D_H;  a.bias[0] = bq + (size_t)i * D_H;  a.C[0] = q;
        a.B[1] = Wk  + (size_t)i * D_IN * D_H;  a.bias[1] = bk + (size_t)i * D_H;  a.C[1] = k;
        a.B[2] = Wv  + (size_t)i * D_IN * D_H;  a.bias[2] = bv + (size_t)i * D_H;  a.C[2] = v;
        a.B[3] = Wr  + (size_t)i * D_IN * D_H;  a.bias[3] = br + (size_t)i * D_H;  a.C[3] = h;
        a.B[4] = Whi + (size_t)i * D_IN * D_H;  a.bias[4] = nullptr;               a.C[4] = hi;
        a.B[5] = Whj + (size_t)i * D_IN * D_H;  a.bias[5] = nullptr;               a.C[5] = hj;
        gemm_x6_kernel<<<dim3(rowTiles, 1, 6), 256>>>(xin, a, M, D_IN);

        // 2) attention scores + global softmax stats
        att_dot_kernel<<<edgeBlocks, 256>>>(ei, q, k, att, E);
        reduce_max_p1<<<512, 256>>>(att, E, part);
        reduce_max_p2<<<1, 512>>>(part, red);
        reduce_sum_p1<<<512, 256>>>(att, red, E, part);
        reduce_sum_p2<<<1, 512>>>(part, red + 1);

        // 3) gated messages scatter-added onto h (= x@Wr + br)
        message_kernel<<<edgeBlocks, 256>>>(ei, ea, v, hi, hj, att, red, h, E);

        // 4) FF MLP with pre-norm residual
        ln128_kernel<<<lnBlocks, 256>>>(h, g1 + (size_t)i * D_H, be1 + (size_t)i * D_H, ln, M);
        gemm_kernel<1><<<dim3(rowTiles, D_FF / 128), 256>>>(
            ln, W1 + (size_t)i * D_H * D_FF, bl1 + (size_t)i * D_FF, nullptr, ff, M, D_FF, D_H);
        gemm_kernel<0><<<dim3(rowTiles, 1), 256>>>(
            ff, W2 + (size_t)i * D_FF * D_H, bl2 + (size_t)i * D_H, h, h2, M, D_H, D_FF);
        ln128_kernel<<<lnBlocks, 256>>>(h2, g2 + (size_t)i * D_H, be2 + (size_t)i * D_H, ln, M);

        // 5) expand back to 1546
        gemm_kernel<0><<<dim3(rowTiles, (D_IN + 127) / 128), 256>>>(
            ln, Wlin, blin, nullptr, X, M, D_IN, D_H);
        xin = X;
    }

    // final: leaky_relu(x @ Wlin2 + blin2)
    gemm_kernel<2><<<dim3(rowTiles, 1), 256>>>(X, Wlin2, blin2, nullptr, out, M, D_H, D_IN);
}

// round 8
// speedup vs baseline: 1.0449x; 1.0449x over previous
#include <cuda_runtime.h>
#include <cuda_bf16.h>
#include <mma.h>
#include <math.h>

using namespace nvcuda;

#define NNODE 20000
#define NEDGE 400000
#define D_IN  1546
#define D_H   128
#define D_FF  512
#define XSTRIDE 1664   // D_IN padded to multiple of 128

#define BM 128
#define BN 128
#define BK 32
#define ALD (BK + 8)   // 40, multiple of 8
#define BLD (BN + 8)   // 136, multiple of 8

// ---------------- scratch (device globals; no allocations) ----------------
__device__ float g_X [NNODE * XSTRIDE]; // updated node features (padded 1546->1664)
__device__ float g_q [NNODE * D_H];
__device__ float g_k [NNODE * D_H];
__device__ float g_v [NNODE * D_H];
__device__ float g_h [NNODE * D_H];    // r accum -> h
__device__ float g_hi[NNODE * D_H];
__device__ float g_hj[NNODE * D_H];
__device__ float g_ln[NNODE * D_H];
__device__ float g_h2[NNODE * D_H];
__device__ float g_ff[NNODE * D_FF];
__device__ float g_att[NEDGE];
__device__ float g_part[512];
__device__ float g_red[2];             // [0]=max, [1]=sum

// ---------------- bf16-split tensor-core GEMM ------------------------------
// C = act(A*B + bias + resid). A: MxK row-major stride lda. B: KxN row-major
// stride N. C stride ldc. fp32 operands split into bf16 hi/lo; products
// hi*hi + hi*lo + lo*hi accumulated in fp32 (error ~2^-17).
// Block tile 128x128x32, 256 threads = 8 warps (4x2), warp tile 32x64.
template <int ACT>  // 0=none, 1=relu, 2=leaky(0.01)
__device__ __forceinline__ void wgemm_body(
    const float* __restrict__ A, int lda,
    const float* __restrict__ B,
    const float* __restrict__ bias, const float* __restrict__ resid,
    float* __restrict__ C, int ldc, int M, int N, int K)
{
    __shared__ __nv_bfloat16 Ahi[BM][ALD];
    __shared__ __nv_bfloat16 Alo[BM][ALD];
    __shared__ __nv_bfloat16 Bhi[BK][BLD];
    __shared__ __nv_bfloat16 Blo[BK][BLD];
    __shared__ float BiasT[16][BN];

    const int tid = threadIdx.x;
    const int wid = tid >> 5;
    const int wm  = wid >> 1;          // 0..3 -> 32-row band
    const int wn  = wid & 1;           // 0..1 -> 64-col band
    const int rowBase = blockIdx.x * BM;
    const int colBase = blockIdx.y * BN;

    wmma::fragment<wmma::accumulator, 16, 16, 16, float> acc[2][4];
#pragma unroll
    for (int mi = 0; mi < 2; mi++)
#pragma unroll
        for (int ni = 0; ni < 4; ni++) wmma::fill_fragment(acc[mi][ni], 0.f);

    // replicated bias tile (16 identical rows) for fragment-based bias add
    for (int l = tid; l < 16 * BN; l += 256) {
        int r = l >> 7, c = l & 127;
        int gc = colBase + c;
        BiasT[r][c] = (bias != nullptr && gc < N) ? bias[gc] : 0.f;
    }

    for (int k0 = 0; k0 < K; k0 += BK) {
#pragma unroll
        for (int jj = 0; jj < 16; jj++) {
            int l = jj * 256 + tid;
            {   // A tile: 128 x 32
                int r = l >> 5, c = l & 31;
                int gr = rowBase + r, gc = k0 + c;
                float xv = (gr < M && gc < K) ? A[(size_t)gr * lda + gc] : 0.f;
                __nv_bfloat16 h = __float2bfloat16(xv);
                Ahi[r][c] = h;
                Alo[r][c] = __float2bfloat16(xv - __bfloat162float(h));
            }
            {   // B tile: 32 x 128
                int r = l >> 7, c = l & 127;
                int gk = k0 + r, gc = colBase + c;
                float xv = (gk < K && gc < N) ? B[(size_t)gk * N + gc] : 0.f;
                __nv_bfloat16 h = __float2bfloat16(xv);
                Bhi[r][c] = h;
                Blo[r][c] = __float2bfloat16(xv - __bfloat162float(h));
            }
        }
        __syncthreads();

#pragma unroll
        for (int ks = 0; ks < BK; ks += 16) {
            wmma::fragment<wmma::matrix_a, 16, 16, 16, __nv_bfloat16, wmma::row_major> ah[2], al[2];
            wmma::fragment<wmma::matrix_b, 16, 16, 16, __nv_bfloat16, wmma::row_major> bh[4], bl[4];
#pragma unroll
            for (int mi = 0; mi < 2; mi++) {
                wmma::load_matrix_sync(ah[mi], &Ahi[wm * 32 + mi * 16][ks], ALD);
                wmma::load_matrix_sync(al[mi], &Alo[wm * 32 + mi * 16][ks], ALD);
            }
#pragma unroll
            for (int ni = 0; ni < 4; ni++) {
                wmma::load_matrix_sync(bh[ni], &Bhi[ks][wn * 64 + ni * 16], BLD);
                wmma::load_matrix_sync(bl[ni], &Blo[ks][wn * 64 + ni * 16], BLD);
            }
#pragma unroll
            for (int mi = 0; mi < 2; mi++)
#pragma unroll
                for (int ni = 0; ni < 4; ni++) {
                    wmma::mma_sync(acc[mi][ni], ah[mi], bh[ni], acc[mi][ni]);
                    wmma::mma_sync(acc[mi][ni], ah[mi], bl[ni], acc[mi][ni]);
                    wmma::mma_sync(acc[mi][ni], al[mi], bh[ni], acc[mi][ni]);
                }
        }
        __syncthreads();
    }

    // epilogue: bias (+resid) + activation, fragment-wise. M % 16 == 0 so every
    // 16-row tile is fully in or fully out of range.
#pragma unroll
    for (int mi = 0; mi < 2; mi++) {
        int grow = rowBase + wm * 32 + mi * 16;
        if (grow >= M) continue;
#pragma unroll
        for (int ni = 0; ni < 4; ni++) {
            int gcol = colBase + wn * 64 + ni * 16;
            wmma::fragment<wmma::accumulator, 16, 16, 16, float> bfr;
            wmma::load_matrix_sync(bfr, &BiasT[0][wn * 64 + ni * 16], BN, wmma::mem_row_major);
            if (resid != nullptr) {
                wmma::fragment<wmma::accumulator, 16, 16, 16, float> rfr;
                wmma::load_matrix_sync(rfr, resid + (size_t)grow * N + gcol, N, wmma::mem_row_major);
#pragma unroll
                for (int i = 0; i < acc[mi][ni].num_elements; i++)
                    acc[mi][ni].x[i] += rfr.x[i];
            }
#pragma unroll
            for (int i = 0; i < acc[mi][ni].num_elements; i++) {
                float v = acc[mi][ni].x[i] + bfr.x[i];
                if (ACT == 1) v = fmaxf(v, 0.f);
                if (ACT == 2) v = (v > 0.f) ? v : 0.01f * v;
                acc[mi][ni].x[i] = v;
            }
            wmma::store_matrix_sync(C + (size_t)grow * ldc + gcol, acc[mi][ni], ldc,
                                    wmma::mem_row_major);
        }
    }
}

template <int ACT>
__global__ __launch_bounds__(256) void wgemm_kernel(
    const float* __restrict__ A, int lda, const float* __restrict__ B,
    const float* bias, const float* resid, float* C, int ldc, int M, int N, int K)
{
    wgemm_body<ACT>(A, lda, B, bias, resid, C, ldc, M, N, K);
}

// 6 projections fused over grid.z (shares A row-tiles through L2). N = D_H.
struct X6Args {
    const float* B[6];
    const float* bias[6];
    float*       C[6];
};
__global__ __launch_bounds__(256) void wgemm_x6_kernel(
    const float* __restrict__ A, int lda, X6Args p, int M, int K)
{
    int z = blockIdx.z;
    wgemm_body<0>(A, lda, p.B[z], p.bias[z], nullptr, p.C[z], D_H, M, D_H, K);
}

// ---------------- LayerNorm over 128, warp per row -------------------------
__global__ __launch_bounds__(256) void ln128_kernel(
    const float* __restrict__ in, const float* __restrict__ gamma,
    const float* __restrict__ beta, float* __restrict__ out, int M)
{
    int row = blockIdx.x * 8 + (threadIdx.x >> 5);
    if (row >= M) return;
    int lane = threadIdx.x & 31;
    const float* p = in + (size_t)row * D_H;
    float v0 = p[lane], v1 = p[lane + 32], v2 = p[lane + 64], v3 = p[lane + 96];
    float s = v0 + v1 + v2 + v3;
#pragma unroll
    for (int o = 16; o > 0; o >>= 1) s += __shfl_xor_sync(0xFFFFFFFFu, s, o);
    float mean = s * (1.f / 128.f);
    float d0 = v0 - mean, d1 = v1 - mean, d2 = v2 - mean, d3 = v3 - mean;
    float ss = d0 * d0 + d1 * d1 + d2 * d2 + d3 * d3;
#pragma unroll
    for (int o = 16; o > 0; o >>= 1) ss += __shfl_xor_sync(0xFFFFFFFFu, ss, o);
    float inv = rsqrtf(ss * (1.f / 128.f) + 1e-5f);
    float* q = out + (size_t)row * D_H;
    q[lane]      = d0 * inv * gamma[lane]      + beta[lane];
    q[lane + 32] = d1 * inv * gamma[lane + 32] + beta[lane + 32];
    q[lane + 64] = d2 * inv * gamma[lane + 64] + beta[lane + 64];
    q[lane + 96] = d3 * inv * gamma[lane + 96] + beta[lane + 96];
}

// ---------------- edge kernels (warp per edge; edge_index is int32) --------
__global__ __launch_bounds__(256) void att_dot_kernel(
    const int* __restrict__ ei, const float* __restrict__ q,
    const float* __restrict__ k, float* __restrict__ att, int E)
{
    int e = (blockIdx.x * blockDim.x + threadIdx.x) >> 5;
    if (e >= E) return;
    int lane = threadIdx.x & 31;
    size_t s = (size_t)ei[e];
    size_t d = (size_t)ei[E + e];
    const float* qp = q + d * D_H;
    const float* kp = k + s * D_H;
    float sum = qp[lane] * kp[lane] + qp[lane + 32] * kp[lane + 32] +
                qp[lane + 64] * kp[lane + 64] + qp[lane + 96] * kp[lane + 96];
#pragma unroll
    for (int o = 16; o > 0; o >>= 1) sum += __shfl_xor_sync(0xFFFFFFFFu, sum, o);
    if (lane == 0) att[e] = sum;
}

__global__ __launch_bounds__(256) void reduce_max_p1(
    const float* __restrict__ att, int E, float* __restrict__ part)
{
    __shared__ float sm[256];
    float m = -INFINITY;
    for (int i = blockIdx.x * 256 + threadIdx.x; i < E; i += gridDim.x * 256)
        m = fmaxf(m, att[i]);
    sm[threadIdx.x] = m;
    __syncthreads();
    for (int o = 128; o > 0; o >>= 1) {
        if (threadIdx.x < o) sm[threadIdx.x] = fmaxf(sm[threadIdx.x], sm[threadIdx.x + o]);
        __syncthreads();
    }
    if (threadIdx.x == 0) part[blockIdx.x] = sm[0];
}

__global__ __launch_bounds__(512) void reduce_max_p2(
    const float* __restrict__ part, float* __restrict__ out)
{
    __shared__ float sm[512];
    sm[threadIdx.x] = part[threadIdx.x];
    __syncthreads();
    for (int o = 256; o > 0; o >>= 1) {
        if (threadIdx.x < o) sm[threadIdx.x] = fmaxf(sm[threadIdx.x], sm[threadIdx.x + o]);
        __syncthreads();
    }
    if (threadIdx.x == 0) out[0] = sm[0];
}

__global__ __launch_bounds__(256) void reduce_sum_p1(
    const float* __restrict__ att, const float* __restrict__ maxp,
    int E, float* __restrict__ part)
{
    __shared__ float sm[256];
    float mx = maxp[0];
    float s = 0.f;
    for (int i = blockIdx.x * 256 + threadIdx.x; i < E; i += gridDim.x * 256)
        s += __expf(att[i] - mx);
    sm[threadIdx.x] = s;
    __syncthreads();
    for (int o = 128; o > 0; o >>= 1) {
        if (threadIdx.x < o) sm[threadIdx.x] += sm[threadIdx.x + o];
        __syncthreads();
    }
    if (threadIdx.x == 0) part[blockIdx.x] = sm[0];
}

__global__ __launch_bounds__(512) void reduce_sum_p2(
    const float* __restrict__ part, float* __restrict__ out)
{
    __shared__ float sm[512];
    sm[threadIdx.x] = part[threadIdx.x];
    __syncthreads();
    for (int o = 256; o > 0; o >>= 1) {
        if (threadIdx.x < o) sm[threadIdx.x] += sm[threadIdx.x + o];
        __syncthreads();
    }
    if (threadIdx.x == 0) out[0] = sm[0];
}

// msg = softmax(att) * v[src] * sigmoid(ea + hi[src] + hj[dst]); scatter-add h[dst]
__global__ __launch_bounds__(256) void message_kernel(
    const int* __restrict__ ei, const float* __restrict__ ea,
    const float* __restrict__ v, const float* __restrict__ hi,
    const float* __restrict__ hj, const float* __restrict__ att,
    const float* __restrict__ red, float* __restrict__ h, int E)
{
    int e = (blockIdx.x * blockDim.x + threadIdx.x) >> 5;
    if (e >= E) return;
    int lane = threadIdx.x & 31;
    size_t s = (size_t)ei[e];
    size_t d = (size_t)ei[E + e];
    float attn = __expf(att[e] - red[0]) * (1.f / red[1]);
    const float* eap = ea + (size_t)e * D_H;
    const float* vp  = v  + s * D_H;
    const float* hip = hi + s * D_H;
    const float* hjp = hj + d * D_H;
    float* hp = h + d * D_H;
#pragma unroll
    for (int c = 0; c < 4; c++) {
        int dim = lane + c * 32;
        float z = eap[dim] + hip[dim] + hjp[dim];
        float gate = 1.f / (1.f + __expf(-z));
        atomicAdd(&hp[dim], attn * vp[dim] * gate);
    }
}

// ---------------- launch ----------------------------------------------------
extern "C" void kernel_launch(void* const* d_in, const int* in_sizes, int n_in,
                              void* d_out, int out_size)
{
    const float* x    = (const float*)d_in[0];
    const int*   ei   = (const int*)d_in[1];   // int32 edge_index [2, E]
    const float* ea   = (const float*)d_in[2];
    const float* Wq   = (const float*)d_in[3];
    const float* bq   = (const float*)d_in[4];
    const float* Wk   = (const float*)d_in[5];
    const float* bk   = (const float*)d_in[6];
    const float* Wv   = (const float*)d_in[7];
    const float* bv   = (const float*)d_in[8];
    const float* Wr   = (const float*)d_in[9];
    const float* br   = (const float*)d_in[10];
    const float* Whi  = (const float*)d_in[11];
    const float* Whj  = (const float*)d_in[12];
    const float* g1   = (const float*)d_in[13];
    const float* be1  = (const float*)d_in[14];
    const float* W1   = (const float*)d_in[15];
    const float* bl1  = (const float*)d_in[16];
    const float* W2   = (const float*)d_in[17];
    const float* bl2  = (const float*)d_in[18];
    const float* g2   = (const float*)d_in[19];
    const float* be2  = (const float*)d_in[20];
    const float* Wlin = (const float*)d_in[21];
    const float* blin = (const float*)d_in[22];
    const float* Wlin2= (const float*)d_in[23];
    const float* blin2= (const float*)d_in[24];
    float* out = (float*)d_out;

    float *X, *q, *k, *v, *h, *hi, *hj, *ln, *h2, *ff, *att, *part, *red;
    cudaGetSymbolAddress((void**)&X,   g_X);
    cudaGetSymbolAddress((void**)&q,   g_q);
    cudaGetSymbolAddress((void**)&k,   g_k);
    cudaGetSymbolAddress((void**)&v,   g_v);
    cudaGetSymbolAddress((void**)&h,   g_h);
    cudaGetSymbolAddress((void**)&hi,  g_hi);
    cudaGetSymbolAddress((void**)&hj,  g_hj);
    cudaGetSymbolAddress((void**)&ln,  g_ln);
    cudaGetSymbolAddress((void**)&h2,  g_h2);
    cudaGetSymbolAddress((void**)&ff,  g_ff);
    cudaGetSymbolAddress((void**)&att, g_att);
    cudaGetSymbolAddress((void**)&part,g_part);
    cudaGetSymbolAddress((void**)&red, g_red);

    const int M = NNODE, E = NEDGE;
    const int rowTiles = (M + 127) / 128;           // 157
    const int edgeBlocks = (E * 32 + 255) / 256;    // warp per edge
    const int lnBlocks = (M + 7) / 8;

    const float* xin = x;
    int lda = D_IN;                                 // layer-2 input is padded X
    for (int i = 0; i < 2; i++) {
        // 1) fused 6-way projection: q,k,v,r(->h),hi,hj
        X6Args a;
        a.B[0] = Wq  + (size_t)i * D_IN * D_H;  a.bias[0] = bq + (size_t)i * D_H;  a.C[0] = q;
        a.B[1] = Wk  + (size_t)i * D_IN * D_H;  a.bias[1] = bk + (size_t)i * D_H;  a.C[1] = k;
        a.B[2] = Wv  + (size_t)i * D_IN * D_H;  a.bias[2] = bv + (size_t)i * D_H;  a.C[2] = v;
        a.B[3] = Wr  + (size_t)i * D_IN * D_H;  a.bias[3] = br + (size_t)i * D_H;  a.C[3] = h;
        a.B[4] = Whi + (size_t)i * D_IN * D_H;  a.bias[4] = nullptr;               a.C[4] = hi;
        a.B[5] = Whj + (size_t)i * D_IN * D_H;  a.bias[5] = nullptr;               a.C[5] = hj;
        wgemm_x6_kernel<<<dim3(rowTiles, 1, 6), 256>>>(xin, lda, a, M, D_IN);

        // 2) attention scores + global softmax stats
        att_dot_kernel<<<edgeBlocks, 256>>>(ei, q, k, att, E);
        reduce_max_p1<<<512, 256>>>(att, E, part);
        reduce_max_p2<<<1, 512>>>(part, red);
        reduce_sum_p1<<<512, 256>>>(att, red, E, part);
        reduce_sum_p2<<<1, 512>>>(part, red + 1);

        // 3) gated messages scatter-added onto h (= x@Wr + br)
        message_kernel<<<edgeBlocks, 256>>>(ei, ea, v, hi, hj, att, red, h, E);

        // 4) FF MLP with pre-norm residual
        ln128_kernel<<<lnBlocks, 256>>>(h, g1 + (size_t)i * D_H, be1 + (size_t)i * D_H, ln, M);
        wgemm_kernel<1><<<dim3(rowTiles, D_FF / 128), 256>>>(
            ln, D_H, W1 + (size_t)i * D_H * D_FF, bl1 + (size_t)i * D_FF, nullptr,
            ff, D_FF, M, D_FF, D_H);
        wgemm_kernel<0><<<dim3(rowTiles, 1), 256>>>(
            ff, D_FF, W2 + (size_t)i * D_FF * D_H, bl2 + (size_t)i * D_H, h,
            h2, D_H, M, D_H, D_FF);
        ln128_kernel<<<lnBlocks, 256>>>(h2, g2 + (size_t)i * D_H, be2 + (size_t)i * D_H, ln, M);

        // 5) expand back to 1546 (into padded-stride X; pad cols written as 0)
        wgemm_kernel<0><<<dim3(rowTiles, XSTRIDE / 128), 256>>>(
            ln, D_H, Wlin, blin, nullptr, X, XSTRIDE, M, D_IN, D_H);
        xin = X;
        lda = XSTRIDE;
    }

    // final: leaky_relu(x @ Wlin2 + blin2)
    wgemm_kernel<2><<<dim3(rowTiles, 1), 256>>>(
        X, XSTRIDE, Wlin2, blin2, nullptr, out, D_H, M, D_H, D_IN);
}

// round 10
// speedup vs baseline: 1.7129x; 1.6392x over previous
#include <cuda_runtime.h>
#include <cuda_bf16.h>
#include <mma.h>
#include <math.h>
#include <cstdint>

using namespace nvcuda;

#define NNODE 20000
#define NEDGE 400000
#define D_IN  1546
#define D_H   128
#define D_FF  512
#define XSTRIDE 1664   // D_IN padded (fp32 X buffer stride)

#define KP_IN 1568     // D_IN padded to mult of 32
#define K3_IN (3 * KP_IN)    // 4704
#define K3_H  (3 * D_H)      // 384
#define K3_FF (3 * D_FF)     // 1536
#define NP_LIN 1664    // Wlin'' col stride (13 tiles * 128)

#define BM 128
#define BN 128
#define BK 32

// ---------------- scratch (device globals; no allocations) ----------------
__device__ float g_X [NNODE * XSTRIDE];
__device__ float g_q [NNODE * D_H];
__device__ float g_k [NNODE * D_H];
__device__ float g_v [NNODE * D_H];
__device__ float g_h [NNODE * D_H];
__device__ float g_hi[NNODE * D_H];
__device__ float g_hj[NNODE * D_H];
__device__ float g_ln[NNODE * D_H];
__device__ float g_h2[NNODE * D_H];
__device__ float g_ff[NNODE * D_FF];
__device__ float g_att[NEDGE];
__device__ float g_part[512];
__device__ float g_red[2];

// bf16 split operands (A'' = [hi|hi|lo], B'' = [hi;hi;lo])
__device__ __nv_bfloat16 g_Xs   [(size_t)NNODE * K3_IN];   // 188 MB
__device__ __nv_bfloat16 g_lns  [(size_t)NNODE * K3_H];
__device__ __nv_bfloat16 g_ffs  [(size_t)NNODE * K3_FF];
__device__ __nv_bfloat16 g_W6s  [(size_t)6 * K3_IN * D_H];
__device__ __nv_bfloat16 g_W1s  [(size_t)K3_H * D_FF];
__device__ __nv_bfloat16 g_W2s  [(size_t)K3_FF * D_H];
__device__ __nv_bfloat16 g_Wlins[(size_t)K3_H * NP_LIN];
__device__ __nv_bfloat16 g_Wl2s [(size_t)K3_IN * D_H];

// ---------------- cp.async helpers -----------------------------------------
__device__ __forceinline__ void cp_async16(void* smem_dst, const void* gsrc, bool pred) {
    uint32_t saddr = (uint32_t)__cvta_generic_to_shared(smem_dst);
    int sz = pred ? 16 : 0;
    asm volatile("cp.async.cg.shared.global [%0], [%1], 16, %2;\n"
                 :: "r"(saddr), "l"(gsrc), "r"(sz));
}
__device__ __forceinline__ void cp_commit() { asm volatile("cp.async.commit_group;\n"); }
template <int NREM>
__device__ __forceinline__ void cp_wait() { asm volatile("cp.async.wait_group %0;\n" :: "n"(NREM)); }

// ---------------- split kernels ---------------------------------------------
// A'' (M x 3Kp): stacked as hi@0, hi@Kp, lo@2Kp
__global__ __launch_bounds__(256) void splitA_kernel(
    const float* __restrict__ in, int lda, int M, int K, int Kp,
    __nv_bfloat16* __restrict__ out)
{
    int idx = blockIdx.x * 256 + threadIdx.x;
    int total = M * Kp;
    if (idx >= total) return;
    int r = idx / Kp, c = idx - r * Kp;
    float v = (c < K) ? in[(size_t)r * lda + c] : 0.f;
    __nv_bfloat16 hi = __float2bfloat16(v);
    __nv_bfloat16 lo = __float2bfloat16(v - __bfloat162float(hi));
    size_t base = (size_t)r * (3 * Kp);
    out[base + c]          = hi;
    out[base + Kp + c]     = hi;
    out[base + 2 * Kp + c] = lo;
}

// B'' (3Kp x NP): rows [hi; lo; hi] paired so stacked product = hi*hi + hi*lo + lo*hi
// pairing: A block order (hi, hi, lo) x B block order (hi, lo, hi)
__global__ __launch_bounds__(256) void splitB_kernel(
    const float* __restrict__ in, int K, int N, int Kp, int NP,
    __nv_bfloat16* __restrict__ out)
{
    int idx = blockIdx.x * 256 + threadIdx.x;
    int total = Kp * NP;
    if (idx >= total) return;
    int r = idx / NP, c = idx - r * NP;
    float v = (r < K && c < N) ? in[(size_t)r * N + c] : 0.f;
    __nv_bfloat16 hi = __float2bfloat16(v);
    __nv_bfloat16 lo = __float2bfloat16(v - __bfloat162float(hi));
    out[(size_t)r * NP + c]            = hi;   // pairs with A hi -> hi*hi
    out[(size_t)(Kp + r) * NP + c]     = lo;   // pairs with A hi -> hi*lo
    out[(size_t)(2 * Kp + r) * NP + c] = hi;   // pairs with A lo -> lo*hi
}

// ---------------- bf16 tensor-core GEMM (2-stage cp.async pipeline) ---------
// C = act(A''*B'' + bias + resid). A'': M x Kt bf16 (stride lda), B'': Kt x NP
// bf16 (stride ldb, fully padded so no col guard). C fp32 stride ldc.
template <int ACT>  // 0=none, 1=relu, 2=leaky(0.01)
__device__ __forceinline__ void bgemm_body(
    const __nv_bfloat16* __restrict__ A, int lda,
    const __nv_bfloat16* __restrict__ B, int ldb,
    const float* __restrict__ bias, const float* __restrict__ resid, int ldr,
    float* __restrict__ C, int ldc, int M, int N, int Kt)
{
    __shared__ __nv_bfloat16 As[2][BM][BK + 8];
    __shared__ __nv_bfloat16 Bs[2][BK][BN + 8];
    __shared__ float BiasT[16][BN];

    const int tid = threadIdx.x;
    const int wid = tid >> 5;
    const int wm  = wid >> 1;
    const int wn  = wid & 1;
    const int rowBase = blockIdx.x * BM;
    const int colBase = blockIdx.y * BN;

    wmma::fragment<wmma::accumulator, 16, 16, 16, float> acc[2][4];
#pragma unroll
    for (int mi = 0; mi < 2; mi++)
#pragma unroll
        for (int ni = 0; ni < 4; ni++) wmma::fill_fragment(acc[mi][ni], 0.f);

    for (int l = tid; l < 16 * BN; l += 256) {
        int r = l >> 7, c = l & 127;
        int gc = colBase + c;
        BiasT[r][c] = (bias != nullptr && gc < N) ? bias[gc] : 0.f;
    }

    const int aCh0 = tid * 2, bCh0 = tid * 2;
    const int nK = Kt / BK;

    {   // prologue: stage 0
        int k0 = 0;
#pragma unroll
        for (int u = 0; u < 2; u++) {
            int ch = aCh0 + u;
            int r = ch >> 2, c8 = (ch & 3) * 8;
            int gr = rowBase + r;
            cp_async16(&As[0][r][c8], A + (size_t)gr * lda + k0 + c8, gr < M);
        }
#pragma unroll
        for (int u = 0; u < 2; u++) {
            int ch = bCh0 + u;
            int r = ch >> 4, c8 = (ch & 15) * 8;
            cp_async16(&Bs[0][r][c8], B + (size_t)(k0 + r) * ldb + colBase + c8, true);
        }
        cp_commit();
    }

    for (int kt = 0; kt < nK; kt++) {
        int cur = kt & 1;
        if (kt + 1 < nK) {
            int nxt = cur ^ 1, k0 = (kt + 1) * BK;
#pragma unroll
            for (int u = 0; u < 2; u++) {
                int ch = aCh0 + u;
                int r = ch >> 2, c8 = (ch & 3) * 8;
                int gr = rowBase + r;
                cp_async16(&As[nxt][r][c8], A + (size_t)gr * lda + k0 + c8, gr < M);
            }
#pragma unroll
            for (int u = 0; u < 2; u++) {
                int ch = bCh0 + u;
                int r = ch >> 4, c8 = (ch & 15) * 8;
                cp_async16(&Bs[nxt][r][c8], B + (size_t)(k0 + r) * ldb + colBase + c8, true);
            }
            cp_commit();
            cp_wait<1>();
        } else {
            cp_wait<0>();
        }
        __syncthreads();

#pragma unroll
        for (int ks = 0; ks < BK; ks += 16) {
            wmma::fragment<wmma::matrix_a, 16, 16, 16, __nv_bfloat16, wmma::row_major> af[2];
            wmma::fragment<wmma::matrix_b, 16, 16, 16, __nv_bfloat16, wmma::row_major> bf[4];
#pragma unroll
            for (int mi = 0; mi < 2; mi++)
                wmma::load_matrix_sync(af[mi], &As[cur][wm * 32 + mi * 16][ks], BK + 8);
#pragma unroll
            for (int ni = 0; ni < 4; ni++)
                wmma::load_matrix_sync(bf[ni], &Bs[cur][ks][wn * 64 + ni * 16], BN + 8);
#pragma unroll
            for (int mi = 0; mi < 2; mi++)
#pragma unroll
                for (int ni = 0; ni < 4; ni++)
                    wmma::mma_sync(acc[mi][ni], af[mi], bf[ni], acc[mi][ni]);
        }
        __syncthreads();
    }

#pragma unroll
    for (int mi = 0; mi < 2; mi++) {
        int grow = rowBase + wm * 32 + mi * 16;
        if (grow >= M) continue;
#pragma unroll
        for (int ni = 0; ni < 4; ni++) {
            int gcol = colBase + wn * 64 + ni * 16;
            wmma::fragment<wmma::accumulator, 16, 16, 16, float> bfr;
            wmma::load_matrix_sync(bfr, &BiasT[0][wn * 64 + ni * 16], BN, wmma::mem_row_major);
            if (resid != nullptr) {
                wmma::fragment<wmma::accumulator, 16, 16, 16, float> rfr;
                wmma::load_matrix_sync(rfr, resid + (size_t)grow * ldr + gcol, ldr,
                                       wmma::mem_row_major);
#pragma unroll
                for (int i = 0; i < acc[mi][ni].num_elements; i++)
                    acc[mi][ni].x[i] += rfr.x[i];
            }
#pragma unroll
            for (int i = 0; i < acc[mi][ni].num_elements; i++) {
                float v = acc[mi][ni].x[i] + bfr.x[i];
                if (ACT == 1) v = fmaxf(v, 0.f);
                if (ACT == 2) v = (v > 0.f) ? v : 0.01f * v;
                acc[mi][ni].x[i] = v;
            }
            wmma::store_matrix_sync(C + (size_t)grow * ldc + gcol, acc[mi][ni], ldc,
                                    wmma::mem_row_major);
        }
    }
}

template <int ACT>
__global__ __launch_bounds__(256) void bgemm_kernel(
    const __nv_bfloat16* __restrict__ A, int lda,
    const __nv_bfloat16* __restrict__ B, int ldb,
    const float* bias, const float* resid, int ldr,
    float* C, int ldc, int M, int N, int Kt)
{
    bgemm_body<ACT>(A, lda, B, ldb, bias, resid, ldr, C, ldc, M, N, Kt);
}

struct X6Args {
    const __nv_bfloat16* B[6];
    const float* bias[6];
    float*       C[6];
};
__global__ __launch_bounds__(256) void bgemm_x6_kernel(
    const __nv_bfloat16* __restrict__ A, X6Args p, int M)
{
    int z = blockIdx.z;
    bgemm_body<0>(A, K3_IN, p.B[z], D_H, p.bias[z], nullptr, 0,
                  p.C[z], D_H, M, D_H, K3_IN);
}

// ---------------- LayerNorm over 128, warp per row -------------------------
__global__ __launch_bounds__(256) void ln128_kernel(
    const float* __restrict__ in, const float* __restrict__ gamma,
    const float* __restrict__ beta, float* __restrict__ out, int M)
{
    int row = blockIdx.x * 8 + (threadIdx.x >> 5);
    if (row >= M) return;
    int lane = threadIdx.x & 31;
    const float* p = in + (size_t)row * D_H;
    float v0 = p[lane], v1 = p[lane + 32], v2 = p[lane + 64], v3 = p[lane + 96];
    float s = v0 + v1 + v2 + v3;
#pragma unroll
    for (int o = 16; o > 0; o >>= 1) s += __shfl_xor_sync(0xFFFFFFFFu, s, o);
    float mean = s * (1.f / 128.f);
    float d0 = v0 - mean, d1 = v1 - mean, d2 = v2 - mean, d3 = v3 - mean;
    float ss = d0 * d0 + d1 * d1 + d2 * d2 + d3 * d3;
#pragma unroll
    for (int o = 16; o > 0; o >>= 1) ss += __shfl_xor_sync(0xFFFFFFFFu, ss, o);
    float inv = rsqrtf(ss * (1.f / 128.f) + 1e-5f);
    float* q = out + (size_t)row * D_H;
    q[lane]      = d0 * inv * gamma[lane]      + beta[lane];
    q[lane + 32] = d1 * inv * gamma[lane + 32] + beta[lane + 32];
    q[lane + 64] = d2 * inv * gamma[lane + 64] + beta[lane + 64];
    q[lane + 96] = d3 * inv * gamma[lane + 96] + beta[lane + 96];
}

// ---------------- edge kernels (warp per edge; edge_index is int32) --------
__global__ __launch_bounds__(256) void att_dot_kernel(
    const int* __restrict__ ei, const float* __restrict__ q,
    const float* __restrict__ k, float* __restrict__ att, int E)
{
    int e = (blockIdx.x * blockDim.x + threadIdx.x) >> 5;
    if (e >= E) return;
    int lane = threadIdx.x & 31;
    size_t s = (size_t)ei[e];
    size_t d = (size_t)ei[E + e];
    const float* qp = q + d * D_H;
    const float* kp = k + s * D_H;
    float sum = qp[lane] * kp[lane] + qp[lane + 32] * kp[lane + 32] +
                qp[lane + 64] * kp[lane + 64] + qp[lane + 96] * kp[lane + 96];
#pragma unroll
    for (int o = 16; o > 0; o >>= 1) sum += __shfl_xor_sync(0xFFFFFFFFu, sum, o);
    if (lane == 0) att[e] = sum;
}

__global__ __launch_bounds__(256) void reduce_max_p1(
    const float* __restrict__ att, int E, float* __restrict__ part)
{
    __shared__ float sm[256];
    float m = -INFINITY;
    for (int i = blockIdx.x * 256 + threadIdx.x; i < E; i += gridDim.x * 256)
        m = fmaxf(m, att[i]);
    sm[threadIdx.x] = m;
    __syncthreads();
    for (int o = 128; o > 0; o >>= 1) {
        if (threadIdx.x < o) sm[threadIdx.x] = fmaxf(sm[threadIdx.x], sm[threadIdx.x + o]);
        __syncthreads();
    }
    if (threadIdx.x == 0) part[blockIdx.x] = sm[0];
}

__global__ __launch_bounds__(512) void reduce_max_p2(
    const float* __restrict__ part, float* __restrict__ out)
{
    __shared__ float sm[512];
    sm[threadIdx.x] = part[threadIdx.x];
    __syncthreads();
    for (int o = 256; o > 0; o >>= 1) {
        if (threadIdx.x < o) sm[threadIdx.x] = fmaxf(sm[threadIdx.x], sm[threadIdx.x + o]);
        __syncthreads();
    }
    if (threadIdx.x == 0) out[0] = sm[0];
}

__global__ __launch_bounds__(256) void reduce_sum_p1(
    const float* __restrict__ att, const float* __restrict__ maxp,
    int E, float* __restrict__ part)
{
    __shared__ float sm[256];
    float mx = maxp[0];
    float s = 0.f;
    for (int i = blockIdx.x * 256 + threadIdx.x; i < E; i += gridDim.x * 256)
        s += __expf(att[i] - mx);
    sm[threadIdx.x] = s;
    __syncthreads();
    for (int o = 128; o > 0; o >>= 1) {
        if (threadIdx.x < o) sm[threadIdx.x] += sm[threadIdx.x + o];
        __syncthreads();
    }
    if (threadIdx.x == 0) part[blockIdx.x] = sm[0];
}

__global__ __launch_bounds__(512) void reduce_sum_p2(
    const float* __restrict__ part, float* __restrict__ out)
{
    __shared__ float sm[512];
    sm[threadIdx.x] = part[threadIdx.x];
    __syncthreads();
    for (int o = 256; o > 0; o >>= 1) {
        if (threadIdx.x < o) sm[threadIdx.x] += sm[threadIdx.x + o];
        __syncthreads();
    }
    if (threadIdx.x == 0) out[0] = sm[0];
}

__global__ __launch_bounds__(256) void message_kernel(
    const int* __restrict__ ei, const float* __restrict__ ea,
    const float* __restrict__ v, const float* __restrict__ hi,
    const float* __restrict__ hj, const float* __restrict__ att,
    const float* __restrict__ red, float* __restrict__ h, int E)
{
    int e = (blockIdx.x * blockDim.x + threadIdx.x) >> 5;
    if (e >= E) return;
    int lane = threadIdx.x & 31;
    size_t s = (size_t)ei[e];
    size_t d = (size_t)ei[E + e];
    float attn = __expf(att[e] - red[0]) * (1.f / red[1]);
    const float* eap = ea + (size_t)e * D_H;
    const float* vp  = v  + s * D_H;
    const float* hip = hi + s * D_H;
    const float* hjp = hj + d * D_H;
    float* hp = h + d * D_H;
#pragma unroll
    for (int c = 0; c < 4; c++) {
        int dim = lane + c * 32;
        float z = eap[dim] + hip[dim] + hjp[dim];
        float gate = 1.f / (1.f + __expf(-z));
        atomicAdd(&hp[dim], attn * vp[dim] * gate);
    }
}

// ---------------- launch ----------------------------------------------------
static inline int cdiv(int a, int b) { return (a + b - 1) / b; }

extern "C" void kernel_launch(void* const* d_in, const int* in_sizes, int n_in,
                              void* d_out, int out_size)
{
    const float* x    = (const float*)d_in[0];
    const int*   ei   = (const int*)d_in[1];
    const float* ea   = (const float*)d_in[2];
    const float* Wq   = (const float*)d_in[3];
    const float* bq   = (const float*)d_in[4];
    const float* Wk   = (const float*)d_in[5];
    const float* bk   = (const float*)d_in[6];
    const float* Wv   = (const float*)d_in[7];
    const float* bv   = (const float*)d_in[8];
    const float* Wr   = (const float*)d_in[9];
    const float* br   = (const float*)d_in[10];
    const float* Whi  = (const float*)d_in[11];
    const float* Whj  = (const float*)d_in[12];
    const float* g1   = (const float*)d_in[13];
    const float* be1  = (const float*)d_in[14];
    const float* W1   = (const float*)d_in[15];
    const float* bl1  = (const float*)d_in[16];
    const float* W2   = (const float*)d_in[17];
    const float* bl2  = (const float*)d_in[18];
    const float* g2   = (const float*)d_in[19];
    const float* be2  = (const float*)d_in[20];
    const float* Wlin = (const float*)d_in[21];
    const float* blin = (const float*)d_in[22];
    const float* Wlin2= (const float*)d_in[23];
    const float* blin2= (const float*)d_in[24];
    float* out = (float*)d_out;

    float *X, *q, *k, *v, *h, *hi, *hj, *ln, *h2, *ff, *att, *part, *red;
    __nv_bfloat16 *Xs, *lns, *ffs, *W6s, *W1s, *W2s, *Wlins, *Wl2s;
    cudaGetSymbolAddress((void**)&X,   g_X);
    cudaGetSymbolAddress((void**)&q,   g_q);
    cudaGetSymbolAddress((void**)&k,   g_k);
    cudaGetSymbolAddress((void**)&v,   g_v);
    cudaGetSymbolAddress((void**)&h,   g_h);
    cudaGetSymbolAddress((void**)&hi,  g_hi);
    cudaGetSymbolAddress((void**)&hj,  g_hj);
    cudaGetSymbolAddress((void**)&ln,  g_ln);
    cudaGetSymbolAddress((void**)&h2,  g_h2);
    cudaGetSymbolAddress((void**)&ff,  g_ff);
    cudaGetSymbolAddress((void**)&att, g_att);
    cudaGetSymbolAddress((void**)&part,g_part);
    cudaGetSymbolAddress((void**)&red, g_red);
    cudaGetSymbolAddress((void**)&Xs,  g_Xs);
    cudaGetSymbolAddress((void**)&lns, g_lns);
    cudaGetSymbolAddress((void**)&ffs, g_ffs);
    cudaGetSymbolAddress((void**)&W6s, g_W6s);
    cudaGetSymbolAddress((void**)&W1s, g_W1s);
    cudaGetSymbolAddress((void**)&W2s, g_W2s);
    cudaGetSymbolAddress((void**)&Wlins, g_Wlins);
    cudaGetSymbolAddress((void**)&Wl2s,  g_Wl2s);

    const int M = NNODE, E = NEDGE;
    const int rowTiles = cdiv(M, BM);
    const int edgeBlocks = (E * 32 + 255) / 256;
    const int lnBlocks = (M + 7) / 8;

    // shared weights: split once
    splitB_kernel<<<cdiv(D_H * NP_LIN, 256), 256>>>(Wlin,  D_H,  D_IN, D_H,  NP_LIN, Wlins);
    splitB_kernel<<<cdiv(KP_IN * D_H, 256), 256>>>(Wlin2, D_IN, D_H,  KP_IN, D_H,   Wl2s);

    const float* xin = x;
    int lda = D_IN;
    for (int i = 0; i < 2; i++) {
        splitA_kernel<<<cdiv(M * KP_IN, 256), 256>>>(xin, lda, M, D_IN, KP_IN, Xs);
        const float* Wp[6] = { Wq + (size_t)i * D_IN * D_H, Wk + (size_t)i * D_IN * D_H,
                               Wv + (size_t)i * D_IN * D_H, Wr + (size_t)i * D_IN * D_H,
                               Whi + (size_t)i * D_IN * D_H, Whj + (size_t)i * D_IN * D_H };
        for (int z = 0; z < 6; z++)
            splitB_kernel<<<cdiv(KP_IN * D_H, 256), 256>>>(
                Wp[z], D_IN, D_H, KP_IN, D_H, W6s + (size_t)z * K3_IN * D_H);

        // 1) fused 6-way projection
        X6Args a;
        for (int z = 0; z < 6; z++) a.B[z] = W6s + (size_t)z * K3_IN * D_H;
        a.bias[0] = bq + (size_t)i * D_H;  a.C[0] = q;
        a.bias[1] = bk + (size_t)i * D_H;  a.C[1] = k;
        a.bias[2] = bv + (size_t)i * D_H;  a.C[2] = v;
        a.bias[3] = br + (size_t)i * D_H;  a.C[3] = h;
        a.bias[4] = nullptr;               a.C[4] = hi;
        a.bias[5] = nullptr;               a.C[5] = hj;
        bgemm_x6_kernel<<<dim3(rowTiles, 1, 6), 256>>>(Xs, a, M);

        // 2) attention + global softmax stats
        att_dot_kernel<<<edgeBlocks, 256>>>(ei, q, k, att, E);
        reduce_max_p1<<<512, 256>>>(att, E, part);
        reduce_max_p2<<<1, 512>>>(part, red);
        reduce_sum_p1<<<512, 256>>>(att, red, E, part);
        reduce_sum_p2<<<1, 512>>>(part, red + 1);

        // 3) gated messages scatter-added onto h
        message_kernel<<<edgeBlocks, 256>>>(ei, ea, v, hi, hj, att, red, h, E);

        // 4) FF MLP with pre-norm residual
        ln128_kernel<<<lnBlocks, 256>>>(h, g1 + (size_t)i * D_H, be1 + (size_t)i * D_H, ln, M);
        splitA_kernel<<<cdiv(M * D_H, 256), 256>>>(ln, D_H, M, D_H, D_H, lns);
        splitB_kernel<<<cdiv(D_H * D_FF, 256), 256>>>(
            W1 + (size_t)i * D_H * D_FF, D_H, D_FF, D_H, D_FF, W1s);
        bgemm_kernel<1><<<dim3(rowTiles, D_FF / BN), 256>>>(
            lns, K3_H, W1s, D_FF, bl1 + (size_t)i * D_FF, nullptr, 0,
            ff, D_FF, M, D_FF, K3_H);
        splitA_kernel<<<cdiv(M * D_FF, 256), 256>>>(ff, D_FF, M, D_FF, D_FF, ffs);
        splitB_kernel<<<cdiv(D_FF * D_H, 256), 256>>>(
            W2 + (size_t)i * D_FF * D_H, D_FF, D_H, D_FF, D_H, W2s);
        bgemm_kernel<0><<<dim3(rowTiles, 1), 256>>>(
            ffs, K3_FF, W2s, D_H, bl2 + (size_t)i * D_H, h, D_H,
            h2, D_H, M, D_H, K3_FF);
        ln128_kernel<<<lnBlocks, 256>>>(h2, g2 + (size_t)i * D_H, be2 + (size_t)i * D_H, ln, M);

        // 5) expand back to 1546 (into padded-stride fp32 X)
        splitA_kernel<<<cdiv(M * D_H, 256), 256>>>(ln, D_H, M, D_H, D_H, lns);
        bgemm_kernel<0><<<dim3(rowTiles, NP_LIN / BN), 256>>>(
            lns, K3_H, Wlins, NP_LIN, blin, nullptr, 0,
            X, XSTRIDE, M, D_IN, K3_H);
        xin = X;
        lda = XSTRIDE;
    }

    // final: leaky_relu(X @ Wlin2 + blin2)
    splitA_kernel<<<cdiv(M * KP_IN, 256), 256>>>(X, XSTRIDE, M, D_IN, KP_IN, Xs);
    bgemm_kernel<2><<<dim3(rowTiles, 1), 256>>>(
        Xs, K3_IN, Wl2s, D_H, blin2, nullptr, 0,
        out, D_H, M, D_H, K3_IN);
}